// round 5
// baseline (speedup 1.0000x reference)
#include <cuda_runtime.h>
#include <math.h>

// Problem constants
#define BSZ 32768
#define TN  50
#define FN  11
static __device__ __constant__ float kDT = 0.1f;

// Scratch (__device__ globals per allocation rules)
__device__ __align__(16) float g_Upk[128*512];            // recurrent weights, gate-interleaved [k][n=j*4+g]
__device__ __align__(16) float g_Wpe[192*512];            // proj+enc weight slice, gate-interleaved
__device__ __align__(16) float g_Wenv[9*512];             // env(6, std-folded) + mc(3) weights, gate-interleaved
__device__ __align__(16) float g_biasI[512];              // b_lstm with mean/std folding, interleaved
__device__ __align__(16) float g_constz[(size_t)BSZ*512]; // per-row time-invariant z part (64 MB)

__device__ __forceinline__ float sigm(float x) { return 1.0f / (1.0f + expf(-x)); }

// ---- packed fp32x2 FMA (sm_100+; ptxas never emits this from C++) ----
union P2 { unsigned long long u; float2 f; };
union Q4 { float4 f; unsigned long long u[2]; };

__device__ __forceinline__ void ffma2(unsigned long long &d,
                                      unsigned long long a,
                                      unsigned long long b)
{
    asm("fma.rn.f32x2 %0, %1, %2, %0;" : "+l"(d) : "l"(a), "l"(b));
}
__device__ __forceinline__ unsigned long long dup2(float x)
{
    unsigned long long r;
    asm("mov.b64 %0, {%1, %1};" : "=l"(r) : "r"(__float_as_uint(x)));
    return r;
}

// 8x8 register-tile GEMM accumulate using FFMA2.
// A[8 rows x K] (SMEM, stride lda), B[K x 8 cols] (SMEM, stride ldb).
// acc[i][c] holds columns (2c, 2c+1) of row i.
__device__ __forceinline__ void gemm_acc2(const float* __restrict__ A, int lda,
                                          const float* __restrict__ Bc, int ldb,
                                          int K, P2 (&acc)[8][4])
{
    for (int k = 0; k < K; k += 4) {
        float4 a[8];
#pragma unroll
        for (int i = 0; i < 8; ++i)
            a[i] = *reinterpret_cast<const float4*>(A + i*lda + k);
        Q4 b0[4], b1[4];
#pragma unroll
        for (int kk = 0; kk < 4; ++kk) {
            const float* bp = Bc + (k+kk)*ldb;
            b0[kk].f = *reinterpret_cast<const float4*>(bp);
            b1[kk].f = *reinterpret_cast<const float4*>(bp + 4);
        }
#pragma unroll
        for (int i = 0; i < 8; ++i) {
            float av[4] = {a[i].x, a[i].y, a[i].z, a[i].w};
#pragma unroll
            for (int kk = 0; kk < 4; ++kk) {
                unsigned long long ad = dup2(av[kk]);
                ffma2(acc[i][0].u, ad, b0[kk].u[0]);
                ffma2(acc[i][1].u, ad, b0[kk].u[1]);
                ffma2(acc[i][2].u, ad, b1[kk].u[0]);
                ffma2(acc[i][3].u, ad, b1[kk].u[1]);
            }
        }
    }
}

// ---------------------------------------------------------------------------
// K1: repack weights. One thread per interleaved column n = j*4+g.
// Folds inv_std into env weights and mean*inv_std into the bias.
// ---------------------------------------------------------------------------
__global__ void pack_kernel(const float* __restrict__ Wl, const float* __restrict__ Ul,
                            const float* __restrict__ bl, const float* __restrict__ mean,
                            const float* __restrict__ var)
{
    int n = blockIdx.x * blockDim.x + threadIdx.x;
    if (n >= 512) return;
    int j = n >> 2, g = n & 3;
    int col = g*128 + j;
    for (int k = 0; k < 128; ++k) g_Upk[k*512 + n] = Ul[k*512 + col];
    for (int k = 0; k < 192; ++k) g_Wpe[k*512 + n] = Wl[k*512 + col];
    float bi = bl[col];
    for (int e = 0; e < 6; ++e) {
        float is = rsqrtf(var[e]);
        float w  = Wl[(192+e)*512 + col];
        g_Wenv[e*512 + n] = w * is;
        bi -= mean[e] * is * w;
    }
    for (int e = 0; e < 3; ++e) g_Wenv[(6+e)*512 + n] = Wl[(198+e)*512 + col];
    g_biasI[n] = bi;
}

// ---------------------------------------------------------------------------
// K2: const_z[row][n] = bias[n] + [proj|enc](row) @ Wpe   (B x 192 x 512 GEMM)
// ---------------------------------------------------------------------------
__global__ void __launch_bounds__(256) const_kernel(const float* __restrict__ proj,
                                                    const float* __restrict__ enc)
{
    extern __shared__ float sm[];
    float* Asm = sm;               // 128 x 196 (proj|enc per row)
    float* Bsm = sm + 128*196;     // 192 x 132
    const int tid = threadIdx.x;
    const int tx = tid & 15, ty = tid >> 4;
    const int row0 = blockIdx.x * 128;

    for (int v = tid; v < 128*64; v += 256) {
        int r = v >> 6, k = v & 63;
        Asm[r*196 + k] = proj[(size_t)(row0+r)*64 + k];
    }
    for (int v = tid; v < 128*128; v += 256) {
        int r = v >> 7, k = v & 127;
        Asm[r*196 + 64 + k] = enc[(size_t)(row0+r)*128 + k];
    }
    __syncthreads();

#pragma unroll 1
    for (int nt = 0; nt < 4; ++nt) {
        for (int v = tid; v < 192*32; v += 256) {
            int k = v >> 5, c4 = (v & 31) << 2;
            *reinterpret_cast<float4*>(Bsm + k*132 + c4) =
                *reinterpret_cast<const float4*>(g_Wpe + k*512 + nt*128 + c4);
        }
        __syncthreads();
        P2 acc[8][4];
#pragma unroll
        for (int i = 0; i < 8; ++i)
#pragma unroll
            for (int c = 0; c < 4; ++c)
                acc[i][c].f = *reinterpret_cast<const float2*>(g_biasI + nt*128 + tx*8 + 2*c);
        gemm_acc2(Asm + ty*8*196, 196, Bsm + tx*8, 132, 192, acc);
        __syncthreads();
#pragma unroll
        for (int i = 0; i < 8; ++i) {
            float* dst = g_constz + (size_t)(row0 + ty*8 + i)*512 + nt*128 + tx*8;
            *reinterpret_cast<float4*>(dst)     = make_float4(acc[i][0].f.x, acc[i][0].f.y, acc[i][1].f.x, acc[i][1].f.y);
            *reinterpret_cast<float4*>(dst + 4) = make_float4(acc[i][2].f.x, acc[i][2].f.y, acc[i][3].f.x, acc[i][3].f.y);
        }
    }
}

// ---------------------------------------------------------------------------
// K3: persistent rollout. 256 CTAs x 128 rows, 256 threads, T loop inside.
// ---------------------------------------------------------------------------
__global__ void __launch_bounds__(256) sim_kernel(
    const float* __restrict__ idm, const float* __restrict__ mcs,
    const float* __restrict__ W1, const float* __restrict__ b1,
    const float* __restrict__ W2, const float* __restrict__ b2,
    const float* __restrict__ W3, const float* __restrict__ b3,
    const float* __restrict__ Wa, const float* __restrict__ ba,
    float* __restrict__ out)
{
    extern __shared__ float sm[];
    float* P0   = sm;                  // h ping  128x132
    float* P1   = P0 + 128*132;        // h pong  128x132
    float* WB   = P1 + 128*132;        // weight tile 128x132
    float* WENV = WB + 128*132;        // 9x512
    float* ENVS = WENV + 9*512;        // 9x128
    float* STV  = ENVS + 9*128;        // ego_v
    float* STX  = STV + 128;           // ego_x
    float* STD  = STX + 128;           // disp
    float* STA  = STD + 128;           // prev act
    float* WAS  = STA + 128;           // Wa (128)
    float* BS   = WAS + 128;           // b1|b2|b3 (384)

    const int tid = threadIdx.x;
    const int tx = tid & 15, ty = tid >> 4;
    const int row0 = blockIdx.x * 128;
    const float dt = kDT;

    for (int v = tid; v < 9*512; v += 256) WENV[v] = g_Wenv[v];
    for (int v = tid; v < 128; v += 256) {
        WAS[v] = Wa[v]; BS[v] = b1[v]; BS[128+v] = b2[v]; BS[256+v] = b3[v];
    }
    if (tid < 128) { STV[tid]=0.f; STX[tid]=0.f; STD[tid]=0.f; STA[tid]=0.f; }
    for (int v = tid; v < 128*132; v += 256) P0[v] = 0.0f;
    const float baV = ba[0];

    float cst[8][8];   // cell state: cst[i][nt*2+jj], j = nt*32 + tx*2 + jj
#pragma unroll
    for (int i = 0; i < 8; ++i)
#pragma unroll
        for (int s = 0; s < 8; ++s) cst[i][s] = 0.0f;
    __syncthreads();

    float* out_d = out;
    float* out_a = out + (size_t)BSZ*TN;

#pragma unroll 1
    for (int t = 0; t < TN; ++t) {
        // ---- Phase A: kinematics + env features (one thread per row) ----
        if (tid < 128) {
            int r = tid;
            int grow = row0 + r;
            const float* s = idm + ((size_t)grow*TN + t)*FN;
            float s0 = s[0], fv = s[1], mv = s[2], s3 = s[3], fx = s[4], mx = s[5], me = s[10];
            float pv = STA[r];
            float nv = (t == 0) ? s0 : (STV[r] + pv*dt);
            float delta = nv*dt + 0.5f*pv*dt*dt;
            float nx = (t == 0) ? s3 : (STX[r] + delta);
            float nd = (t == 0) ? 0.0f : (STD[r] + delta);
            ENVS[0*128 + r] = nv;
            ENVS[1*128 + r] = fv;
            ENVS[2*128 + r] = nv - fv;
            ENVS[3*128 + r] = fx - nx;
            ENVS[4*128 + r] = (nv - mv)*me;
            ENVS[5*128 + r] = (mx - nx)*me + (1.0f - me)*100.0f;
            const float* mcp = mcs + ((size_t)grow*TN + t)*3;
            ENVS[6*128 + r] = mcp[0];
            ENVS[7*128 + r] = mcp[1];
            ENVS[8*128 + r] = mcp[2];
            STV[r] = nv; STX[r] = nx; STD[r] = nd;
            out_d[(size_t)grow*TN + t] = nd;
        }
        __syncthreads();

        float* Hold = (t & 1) ? P1 : P0;
        float* Hnew = (t & 1) ? P0 : P1;

        // ---- z GEMM: 4 tiles of 128 interleaved cols (32 j x 4 gates each) ----
#pragma unroll
        for (int nt = 0; nt < 4; ++nt) {
            for (int v = tid; v < 128*32; v += 256) {
                int k = v >> 5, c4 = (v & 31) << 2;
                *reinterpret_cast<float4*>(WB + k*132 + c4) =
                    *reinterpret_cast<const float4*>(g_Upk + k*512 + nt*128 + c4);
            }
            __syncthreads();
            P2 acc[8][4];
            const float* czr = g_constz + (size_t)(row0 + ty*8)*512 + nt*128 + tx*8;
#pragma unroll
            for (int i = 0; i < 8; ++i) {
                Q4 c0, c1;
                c0.f = *reinterpret_cast<const float4*>(czr + (size_t)i*512);
                c1.f = *reinterpret_cast<const float4*>(czr + (size_t)i*512 + 4);
                acc[i][0].u = c0.u[0]; acc[i][1].u = c0.u[1];
                acc[i][2].u = c1.u[0]; acc[i][3].u = c1.u[1];
            }
#pragma unroll
            for (int e = 0; e < 9; ++e) {
                const float* wp = WENV + e*512 + nt*128 + tx*8;
                Q4 w0, w1;
                w0.f = *reinterpret_cast<const float4*>(wp);
                w1.f = *reinterpret_cast<const float4*>(wp + 4);
#pragma unroll
                for (int i = 0; i < 8; ++i) {
                    unsigned long long ev = dup2(ENVS[e*128 + ty*8 + i]);
                    ffma2(acc[i][0].u, ev, w0.u[0]);
                    ffma2(acc[i][1].u, ev, w0.u[1]);
                    ffma2(acc[i][2].u, ev, w1.u[0]);
                    ffma2(acc[i][3].u, ev, w1.u[1]);
                }
            }
            gemm_acc2(Hold + ty*8*132, 132, WB + tx*8, 132, 128, acc);
            __syncthreads();
            // gate epilogue: cols are (j,gate) interleaved -> pair (zi,zf),(zg,zo)
#pragma unroll
            for (int i = 0; i < 8; ++i) {
#pragma unroll
                for (int jj = 0; jj < 2; ++jj) {
                    float zi = acc[i][jj*2+0].f.x, zf = acc[i][jj*2+0].f.y;
                    float zg = acc[i][jj*2+1].f.x, zo = acc[i][jj*2+1].f.y;
                    float c2 = sigm(zf)*cst[i][nt*2+jj] + sigm(zi)*tanhf(zg);
                    cst[i][nt*2+jj] = c2;
                    Hnew[(ty*8+i)*132 + nt*32 + tx*2 + jj] = sigm(zo)*tanhf(c2);
                }
            }
        }
        __syncthreads();

        // ---- FF chain: x1 -> x2 -> x3 (LReLU), in Hold (old h is dead) ----
        const float* Aff = Hnew;
#pragma unroll 1
        for (int L = 0; L < 3; ++L) {
            const float* Wg = (L == 0) ? W1 : (L == 1) ? W2 : W3;
            const float* bb = BS + L*128;
            for (int v = tid; v < 128*32; v += 256) {
                int k = v >> 5, c4 = (v & 31) << 2;
                *reinterpret_cast<float4*>(WB + k*132 + c4) =
                    *reinterpret_cast<const float4*>(Wg + k*128 + c4);
            }
            __syncthreads();
            P2 acc[8][4];
#pragma unroll
            for (int i = 0; i < 8; ++i)
#pragma unroll
                for (int c = 0; c < 4; ++c)
                    acc[i][c].f = *reinterpret_cast<const float2*>(bb + tx*8 + 2*c);
            gemm_acc2(Aff + ty*8*132, 132, WB + tx*8, 132, 128, acc);
            __syncthreads();
#pragma unroll
            for (int i = 0; i < 8; ++i) {
#pragma unroll
                for (int c = 0; c < 4; ++c) {
                    float vx = acc[i][c].f.x, vy = acc[i][c].f.y;
                    float2 r;
                    r.x = (vx > 0.0f) ? vx : 0.3f*vx;
                    r.y = (vy > 0.0f) ? vy : 0.3f*vy;
                    *reinterpret_cast<float2*>(Hold + (ty*8+i)*132 + tx*8 + 2*c) = r;
                }
            }
            __syncthreads();
            Aff = Hold;   // layers 2,3 run in place (regs hold full tile before write)
        }

        // ---- act head: per-row dot(x3, Wa), 2 threads/row + shfl reduce ----
        {
            int r = tid >> 1, half = tid & 1;
            const float* xr = Hold + r*132 + half*64;
            const float* wr = WAS + half*64;
            float p = 0.0f;
#pragma unroll
            for (int k = 0; k < 64; k += 4) {
                float4 x = *reinterpret_cast<const float4*>(xr + k);
                float4 w = *reinterpret_cast<const float4*>(wr + k);
                p += x.x*w.x + x.y*w.y + x.z*w.z + x.w*w.w;
            }
            p += __shfl_xor_sync(0xFFFFFFFFu, p, 1);
            if (half == 0) {
                float a = p + baV;
                STA[r] = a;
                out_a[(size_t)(row0 + r)*TN + t] = a;
            }
        }
        __syncthreads();
    }
}

// ---------------------------------------------------------------------------
extern "C" void kernel_launch(void* const* d_in, const int* in_sizes, int n_in,
                              void* d_out, int out_size)
{
    const float* proj = (const float*)d_in[0];
    const float* enc  = (const float*)d_in[1];
    const float* idm  = (const float*)d_in[2];
    const float* mcs  = (const float*)d_in[3];
    const float* mean = (const float*)d_in[4];
    const float* var  = (const float*)d_in[5];
    const float* Wl   = (const float*)d_in[6];
    const float* Ul   = (const float*)d_in[7];
    const float* bl   = (const float*)d_in[8];
    const float* W1   = (const float*)d_in[9];
    const float* b1   = (const float*)d_in[10];
    const float* W2   = (const float*)d_in[11];
    const float* b2   = (const float*)d_in[12];
    const float* W3   = (const float*)d_in[13];
    const float* b3   = (const float*)d_in[14];
    const float* Wa   = (const float*)d_in[15];
    const float* ba   = (const float*)d_in[16];
    float* out = (float*)d_out;

    const int constSmem = (128*196 + 192*132) * (int)sizeof(float);
    const int mainSmem  = (3*128*132 + 9*512 + 9*128 + 4*128 + 128 + 384) * (int)sizeof(float);
    cudaFuncSetAttribute(const_kernel, cudaFuncAttributeMaxDynamicSharedMemorySize, constSmem);
    cudaFuncSetAttribute(sim_kernel,   cudaFuncAttributeMaxDynamicSharedMemorySize, mainSmem);

    pack_kernel<<<2, 256>>>(Wl, Ul, bl, mean, var);
    const_kernel<<<BSZ/128, 256, constSmem>>>(proj, enc);
    sim_kernel<<<BSZ/128, 256, mainSmem>>>(idm, mcs, W1, b1, W2, b2, W3, b3, Wa, ba, out);
}

// round 6
// speedup vs baseline: 1.0039x; 1.0039x over previous
#include <cuda_runtime.h>
#include <math.h>

// Problem constants
#define BSZ 32768
#define TN  50
#define FN  11
static __device__ __constant__ float kDT = 0.1f;

// Scratch (__device__ globals per allocation rules)
__device__ __align__(16) float g_Upk[128*512];            // recurrent weights, gate-interleaved [k][n=j*4+g]
__device__ __align__(16) float g_Wpe[192*512];            // proj+enc weight slice, gate-interleaved
__device__ __align__(16) float g_Wenv[9*512];             // env(6, std-folded) + mc(3) weights, gate-interleaved
__device__ __align__(16) float g_biasI[512];              // b_lstm with mean/std folding, interleaved
__device__ __align__(16) float g_constz[(size_t)BSZ*512]; // per-row time-invariant z part (64 MB)

__device__ __forceinline__ float sigm(float x) { return 1.0f / (1.0f + expf(-x)); }

// ---- packed fp32x2 FMA (sm_100+; ptxas never emits this from C++) ----
union P2 { unsigned long long u; float2 f; };
union Q4 { float4 f; unsigned long long u[2]; };

__device__ __forceinline__ void ffma2(unsigned long long &d,
                                      unsigned long long a,
                                      unsigned long long b)
{
    asm("fma.rn.f32x2 %0, %1, %2, %0;" : "+l"(d) : "l"(a), "l"(b));
}
__device__ __forceinline__ unsigned long long dup2(float x)
{
    unsigned long long r;
    asm("mov.b64 %0, {%1, %1};" : "=l"(r) : "r"(__float_as_uint(x)));
    return r;
}

// 8x8 register-tile GEMM accumulate using FFMA2.
// A[8 rows x K] (SMEM, stride lda), B[K x 8 cols] (SMEM, stride ldb).
// acc[i][c] holds columns (2c, 2c+1) of row i.
__device__ __forceinline__ void gemm_acc2(const float* __restrict__ A, int lda,
                                          const float* __restrict__ Bc, int ldb,
                                          int K, P2 (&acc)[8][4])
{
    for (int k = 0; k < K; k += 4) {
        float4 a[8];
#pragma unroll
        for (int i = 0; i < 8; ++i)
            a[i] = *reinterpret_cast<const float4*>(A + i*lda + k);
        Q4 b0[4], b1[4];
#pragma unroll
        for (int kk = 0; kk < 4; ++kk) {
            const float* bp = Bc + (k+kk)*ldb;
            b0[kk].f = *reinterpret_cast<const float4*>(bp);
            b1[kk].f = *reinterpret_cast<const float4*>(bp + 4);
        }
#pragma unroll
        for (int i = 0; i < 8; ++i) {
            float av[4] = {a[i].x, a[i].y, a[i].z, a[i].w};
#pragma unroll
            for (int kk = 0; kk < 4; ++kk) {
                unsigned long long ad = dup2(av[kk]);
                ffma2(acc[i][0].u, ad, b0[kk].u[0]);
                ffma2(acc[i][1].u, ad, b0[kk].u[1]);
                ffma2(acc[i][2].u, ad, b1[kk].u[0]);
                ffma2(acc[i][3].u, ad, b1[kk].u[1]);
            }
        }
    }
}

// ---------------------------------------------------------------------------
// K1: repack weights. One thread per interleaved column n = j*4+g.
// Folds inv_std into env weights and mean*inv_std into the bias.
// ---------------------------------------------------------------------------
__global__ void pack_kernel(const float* __restrict__ Wl, const float* __restrict__ Ul,
                            const float* __restrict__ bl, const float* __restrict__ mean,
                            const float* __restrict__ var)
{
    int n = blockIdx.x * blockDim.x + threadIdx.x;
    if (n >= 512) return;
    int j = n >> 2, g = n & 3;
    int col = g*128 + j;
    for (int k = 0; k < 128; ++k) g_Upk[k*512 + n] = Ul[k*512 + col];
    for (int k = 0; k < 192; ++k) g_Wpe[k*512 + n] = Wl[k*512 + col];
    float bi = bl[col];
    for (int e = 0; e < 6; ++e) {
        float is = rsqrtf(var[e]);
        float w  = Wl[(192+e)*512 + col];
        g_Wenv[e*512 + n] = w * is;
        bi -= mean[e] * is * w;
    }
    for (int e = 0; e < 3; ++e) g_Wenv[(6+e)*512 + n] = Wl[(198+e)*512 + col];
    g_biasI[n] = bi;
}

// ---------------------------------------------------------------------------
// K2: const_z[row][n] = bias[n] + [proj|enc](row) @ Wpe   (B x 192 x 512 GEMM)
// ---------------------------------------------------------------------------
__global__ void __launch_bounds__(256) const_kernel(const float* __restrict__ proj,
                                                    const float* __restrict__ enc)
{
    extern __shared__ float sm[];
    float* Asm = sm;               // 128 x 196 (proj|enc per row)
    float* Bsm = sm + 128*196;     // 192 x 132
    const int tid = threadIdx.x;
    const int tx = tid & 15, ty = tid >> 4;
    const int row0 = blockIdx.x * 128;

    for (int v = tid; v < 128*64; v += 256) {
        int r = v >> 6, k = v & 63;
        Asm[r*196 + k] = proj[(size_t)(row0+r)*64 + k];
    }
    for (int v = tid; v < 128*128; v += 256) {
        int r = v >> 7, k = v & 127;
        Asm[r*196 + 64 + k] = enc[(size_t)(row0+r)*128 + k];
    }
    __syncthreads();

#pragma unroll 1
    for (int nt = 0; nt < 4; ++nt) {
        for (int v = tid; v < 192*32; v += 256) {
            int k = v >> 5, c4 = (v & 31) << 2;
            *reinterpret_cast<float4*>(Bsm + k*132 + c4) =
                *reinterpret_cast<const float4*>(g_Wpe + k*512 + nt*128 + c4);
        }
        __syncthreads();
        P2 acc[8][4];
#pragma unroll
        for (int i = 0; i < 8; ++i)
#pragma unroll
            for (int c = 0; c < 4; ++c)
                acc[i][c].f = *reinterpret_cast<const float2*>(g_biasI + nt*128 + tx*8 + 2*c);
        gemm_acc2(Asm + ty*8*196, 196, Bsm + tx*8, 132, 192, acc);
        __syncthreads();
#pragma unroll
        for (int i = 0; i < 8; ++i) {
            float* dst = g_constz + (size_t)(row0 + ty*8 + i)*512 + nt*128 + tx*8;
            *reinterpret_cast<float4*>(dst)     = make_float4(acc[i][0].f.x, acc[i][0].f.y, acc[i][1].f.x, acc[i][1].f.y);
            *reinterpret_cast<float4*>(dst + 4) = make_float4(acc[i][2].f.x, acc[i][2].f.y, acc[i][3].f.x, acc[i][3].f.y);
        }
    }
}

// ---------------------------------------------------------------------------
// K3: persistent rollout. 256 CTAs x 128 rows, 256 threads, T loop inside.
// ---------------------------------------------------------------------------
__global__ void __launch_bounds__(256) sim_kernel(
    const float* __restrict__ idm, const float* __restrict__ mcs,
    const float* __restrict__ W1, const float* __restrict__ b1,
    const float* __restrict__ W2, const float* __restrict__ b2,
    const float* __restrict__ W3, const float* __restrict__ b3,
    const float* __restrict__ Wa, const float* __restrict__ ba,
    float* __restrict__ out)
{
    extern __shared__ float sm[];
    float* P0   = sm;                  // h ping  128x132
    float* P1   = P0 + 128*132;        // h pong  128x132
    float* WB   = P1 + 128*132;        // weight tile 128x132
    float* WENV = WB + 128*132;        // 9x512
    float* ENVS = WENV + 9*512;        // 9x128
    float* STV  = ENVS + 9*128;        // ego_v
    float* STX  = STV + 128;           // ego_x
    float* STD  = STX + 128;           // disp
    float* STA  = STD + 128;           // prev act
    float* WAS  = STA + 128;           // Wa (128)
    float* BS   = WAS + 128;           // b1|b2|b3 (384)

    const int tid = threadIdx.x;
    const int tx = tid & 15, ty = tid >> 4;
    const int row0 = blockIdx.x * 128;
    const float dt = kDT;

    for (int v = tid; v < 9*512; v += 256) WENV[v] = g_Wenv[v];
    for (int v = tid; v < 128; v += 256) {
        WAS[v] = Wa[v]; BS[v] = b1[v]; BS[128+v] = b2[v]; BS[256+v] = b3[v];
    }
    if (tid < 128) { STV[tid]=0.f; STX[tid]=0.f; STD[tid]=0.f; STA[tid]=0.f; }
    for (int v = tid; v < 128*132; v += 256) P0[v] = 0.0f;
    const float baV = ba[0];

    float cst[8][8];   // cell state: cst[i][nt*2+jj], j = nt*32 + tx*2 + jj
#pragma unroll
    for (int i = 0; i < 8; ++i)
#pragma unroll
        for (int s = 0; s < 8; ++s) cst[i][s] = 0.0f;
    __syncthreads();

    float* out_d = out;
    float* out_a = out + (size_t)BSZ*TN;

#pragma unroll 1
    for (int t = 0; t < TN; ++t) {
        // ---- Phase A: kinematics + env features (one thread per row) ----
        if (tid < 128) {
            int r = tid;
            int grow = row0 + r;
            const float* s = idm + ((size_t)grow*TN + t)*FN;
            float s0 = s[0], fv = s[1], mv = s[2], s3 = s[3], fx = s[4], mx = s[5], me = s[10];
            float pv = STA[r];
            float nv = (t == 0) ? s0 : (STV[r] + pv*dt);
            float delta = nv*dt + 0.5f*pv*dt*dt;
            float nx = (t == 0) ? s3 : (STX[r] + delta);
            float nd = (t == 0) ? 0.0f : (STD[r] + delta);
            ENVS[0*128 + r] = nv;
            ENVS[1*128 + r] = fv;
            ENVS[2*128 + r] = nv - fv;
            ENVS[3*128 + r] = fx - nx;
            ENVS[4*128 + r] = (nv - mv)*me;
            ENVS[5*128 + r] = (mx - nx)*me + (1.0f - me)*100.0f;
            const float* mcp = mcs + ((size_t)grow*TN + t)*3;
            ENVS[6*128 + r] = mcp[0];
            ENVS[7*128 + r] = mcp[1];
            ENVS[8*128 + r] = mcp[2];
            STV[r] = nv; STX[r] = nx; STD[r] = nd;
            out_d[(size_t)grow*TN + t] = nd;
        }
        __syncthreads();

        float* Hold = (t & 1) ? P1 : P0;
        float* Hnew = (t & 1) ? P0 : P1;

        // ---- z GEMM: 4 tiles of 128 interleaved cols (32 j x 4 gates each) ----
#pragma unroll
        for (int nt = 0; nt < 4; ++nt) {
            for (int v = tid; v < 128*32; v += 256) {
                int k = v >> 5, c4 = (v & 31) << 2;
                *reinterpret_cast<float4*>(WB + k*132 + c4) =
                    *reinterpret_cast<const float4*>(g_Upk + k*512 + nt*128 + c4);
            }
            __syncthreads();
            P2 acc[8][4];
            const float* czr = g_constz + (size_t)(row0 + ty*8)*512 + nt*128 + tx*8;
#pragma unroll
            for (int i = 0; i < 8; ++i) {
                Q4 c0, c1;
                c0.f = *reinterpret_cast<const float4*>(czr + (size_t)i*512);
                c1.f = *reinterpret_cast<const float4*>(czr + (size_t)i*512 + 4);
                acc[i][0].u = c0.u[0]; acc[i][1].u = c0.u[1];
                acc[i][2].u = c1.u[0]; acc[i][3].u = c1.u[1];
            }
#pragma unroll
            for (int e = 0; e < 9; ++e) {
                const float* wp = WENV + e*512 + nt*128 + tx*8;
                Q4 w0, w1;
                w0.f = *reinterpret_cast<const float4*>(wp);
                w1.f = *reinterpret_cast<const float4*>(wp + 4);
#pragma unroll
                for (int i = 0; i < 8; ++i) {
                    unsigned long long ev = dup2(ENVS[e*128 + ty*8 + i]);
                    ffma2(acc[i][0].u, ev, w0.u[0]);
                    ffma2(acc[i][1].u, ev, w0.u[1]);
                    ffma2(acc[i][2].u, ev, w1.u[0]);
                    ffma2(acc[i][3].u, ev, w1.u[1]);
                }
            }
            gemm_acc2(Hold + ty*8*132, 132, WB + tx*8, 132, 128, acc);
            __syncthreads();
            // gate epilogue: cols are (j,gate) interleaved -> pair (zi,zf),(zg,zo)
#pragma unroll
            for (int i = 0; i < 8; ++i) {
#pragma unroll
                for (int jj = 0; jj < 2; ++jj) {
                    float zi = acc[i][jj*2+0].f.x, zf = acc[i][jj*2+0].f.y;
                    float zg = acc[i][jj*2+1].f.x, zo = acc[i][jj*2+1].f.y;
                    float c2 = sigm(zf)*cst[i][nt*2+jj] + sigm(zi)*tanhf(zg);
                    cst[i][nt*2+jj] = c2;
                    Hnew[(ty*8+i)*132 + nt*32 + tx*2 + jj] = sigm(zo)*tanhf(c2);
                }
            }
        }
        __syncthreads();

        // ---- FF chain: x1 -> x2 -> x3 (LReLU), in Hold (old h is dead) ----
        const float* Aff = Hnew;
#pragma unroll 1
        for (int L = 0; L < 3; ++L) {
            const float* Wg = (L == 0) ? W1 : (L == 1) ? W2 : W3;
            const float* bb = BS + L*128;
            for (int v = tid; v < 128*32; v += 256) {
                int k = v >> 5, c4 = (v & 31) << 2;
                *reinterpret_cast<float4*>(WB + k*132 + c4) =
                    *reinterpret_cast<const float4*>(Wg + k*128 + c4);
            }
            __syncthreads();
            P2 acc[8][4];
#pragma unroll
            for (int i = 0; i < 8; ++i)
#pragma unroll
                for (int c = 0; c < 4; ++c)
                    acc[i][c].f = *reinterpret_cast<const float2*>(bb + tx*8 + 2*c);
            gemm_acc2(Aff + ty*8*132, 132, WB + tx*8, 132, 128, acc);
            __syncthreads();
#pragma unroll
            for (int i = 0; i < 8; ++i) {
#pragma unroll
                for (int c = 0; c < 4; ++c) {
                    float vx = acc[i][c].f.x, vy = acc[i][c].f.y;
                    float2 r;
                    r.x = (vx > 0.0f) ? vx : 0.3f*vx;
                    r.y = (vy > 0.0f) ? vy : 0.3f*vy;
                    *reinterpret_cast<float2*>(Hold + (ty*8+i)*132 + tx*8 + 2*c) = r;
                }
            }
            __syncthreads();
            Aff = Hold;   // layers 2,3 run in place (regs hold full tile before write)
        }

        // ---- act head: per-row dot(x3, Wa), 2 threads/row + shfl reduce ----
        {
            int r = tid >> 1, half = tid & 1;
            const float* xr = Hold + r*132 + half*64;
            const float* wr = WAS + half*64;
            float p = 0.0f;
#pragma unroll
            for (int k = 0; k < 64; k += 4) {
                float4 x = *reinterpret_cast<const float4*>(xr + k);
                float4 w = *reinterpret_cast<const float4*>(wr + k);
                p += x.x*w.x + x.y*w.y + x.z*w.z + x.w*w.w;
            }
            p += __shfl_xor_sync(0xFFFFFFFFu, p, 1);
            if (half == 0) {
                float a = p + baV;
                STA[r] = a;
                out_a[(size_t)(row0 + r)*TN + t] = a;
            }
        }
        __syncthreads();
    }
}

// ---------------------------------------------------------------------------
extern "C" void kernel_launch(void* const* d_in, const int* in_sizes, int n_in,
                              void* d_out, int out_size)
{
    const float* proj = (const float*)d_in[0];
    const float* enc  = (const float*)d_in[1];
    const float* idm  = (const float*)d_in[2];
    const float* mcs  = (const float*)d_in[3];
    const float* mean = (const float*)d_in[4];
    const float* var  = (const float*)d_in[5];
    const float* Wl   = (const float*)d_in[6];
    const float* Ul   = (const float*)d_in[7];
    const float* bl   = (const float*)d_in[8];
    const float* W1   = (const float*)d_in[9];
    const float* b1   = (const float*)d_in[10];
    const float* W2   = (const float*)d_in[11];
    const float* b2   = (const float*)d_in[12];
    const float* W3   = (const float*)d_in[13];
    const float* b3   = (const float*)d_in[14];
    const float* Wa   = (const float*)d_in[15];
    const float* ba   = (const float*)d_in[16];
    float* out = (float*)d_out;

    const int constSmem = (128*196 + 192*132) * (int)sizeof(float);
    const int mainSmem  = (3*128*132 + 9*512 + 9*128 + 4*128 + 128 + 384) * (int)sizeof(float);
    cudaFuncSetAttribute(const_kernel, cudaFuncAttributeMaxDynamicSharedMemorySize, constSmem);
    cudaFuncSetAttribute(sim_kernel,   cudaFuncAttributeMaxDynamicSharedMemorySize, mainSmem);

    pack_kernel<<<2, 256>>>(Wl, Ul, bl, mean, var);
    const_kernel<<<BSZ/128, 256, constSmem>>>(proj, enc);
    sim_kernel<<<BSZ/128, 256, mainSmem>>>(idm, mcs, W1, b1, W2, b2, W3, b3, Wa, ba, out);
}